// round 12
// baseline (speedup 1.0000x reference)
#include <cuda_runtime.h>

// SSIM loss, fused separable 11x11 gaussian blur + ssim map + mean reduce.
// R12: throughput-bound regime confirmed (R10 occ70 == R11 occ94 == 204us;
// issue 75%, L1 84%). Cut work/output instead:
//  - TW 32->64 (TH=22): halo area ratio 1.91 -> 1.68 (-12% P1/P2 work)
//  - P2 windows 4->8 output cols (256 balanced tasks): reads/out -37%
//  - P3 4 row-groups per col (256 tasks, 5-6 rows each): reads/out -35%
// Total smem traffic -31%/output. smem 52.2KB -> 4 CTAs/SM (50% occ, cap 64
// regs). Bet: >=50% occ suffices in throughput regime (R10/R11 evidence).

#define IMG      512
#define TW       64
#define TH       22
#define HALO     5
#define INW      74          // TW + 2*HALO
#define INWP     76          // padded row stride
#define INH      32          // TH + 2*HALO
#define NT       256
#define HPLANE   (INH * TW)  // 2048 floats per blurred field

#define GX       8           // 512/64
#define GY       24          // 24*22 = 528 rows, tail masked
#define PL       96
#define NB       (GX * GY * PL)   // 18432 = 18*1024

#define SMEM_FLOATS (2 * INH * INWP + 4 * HPLANE)   // 4864 + 8192 = 13056
#define SMEM_BYTES  (SMEM_FLOATS * 4)               // 52224

__device__ float g_part[NB];
__device__ float g_part2[18];

// 1D gaussian, sigma=1.5, K=11, normalized. Constant indices fold to
// FFMA immediates (rt_SMSP=1 imm-form).
__device__ __forceinline__ constexpr float gw(int k) {
    switch (k) {
        case 0:  return 0.00102838f;
        case 1:  return 0.00759877f;
        case 2:  return 0.03600077f;
        case 3:  return 0.10936069f;
        case 4:  return 0.21300554f;
        case 5:  return 0.26601173f;
        case 6:  return 0.21300554f;
        case 7:  return 0.10936069f;
        case 8:  return 0.03600077f;
        case 9:  return 0.00759877f;
        case 10: return 0.00102838f;
    }
    return 0.0f;
}

// Horizontal 11-tap blur of one field: 20-float window -> 8 outputs of
// {B(x), B(x^2)} stored to planes d0, d1.
__device__ __forceinline__ void hblur8(const float* __restrict__ src,
                                       float* __restrict__ d0,
                                       float* __restrict__ d1,
                                       int row, int c8) {
    float a[20];
    {
        const float4* a4 = (const float4*)(src + row * INWP + c8);
        ((float4*)a)[0] = a4[0]; ((float4*)a)[1] = a4[1];
        ((float4*)a)[2] = a4[2]; ((float4*)a)[3] = a4[3];
        ((float4*)a)[4] = a4[4];
    }
    float f[8]  = {0.f,0.f,0.f,0.f,0.f,0.f,0.f,0.f};
    float f2[8] = {0.f,0.f,0.f,0.f,0.f,0.f,0.f,0.f};
    #pragma unroll
    for (int i = 0; i < 18; i++) {
        float v = a[i];
        float vv = v * v;
        #pragma unroll
        for (int j = 0; j < 8; j++) {
            int k = i - j;
            if (k >= 0 && k < 11) {
                float w = gw(k);
                f[j]  = fmaf(v,  w, f[j]);
                f2[j] = fmaf(vv, w, f2[j]);
            }
        }
    }
    float* h0 = d0 + row * TW + c8;
    float* h1 = d1 + row * TW + c8;
    *(float4*)(h0 + 0) = make_float4(f[0],  f[1],  f[2],  f[3]);
    *(float4*)(h0 + 4) = make_float4(f[4],  f[5],  f[6],  f[7]);
    *(float4*)(h1 + 0) = make_float4(f2[0], f2[1], f2[2], f2[3]);
    *(float4*)(h1 + 4) = make_float4(f2[4], f2[5], f2[6], f2[7]);
}

__global__ __launch_bounds__(NT, 4)
void ssim_main(const float* __restrict__ img1, const float* __restrict__ img2) {
    extern __shared__ float smem[];
    float* ss = smem;                       // s = x1+x2 tile [INH][INWP]
    float* sd = smem + INH * INWP;          // d = x1-x2 tile
    float* sh = smem + 2 * INH * INWP;      // 4 planar fields [INH][TW]
    __shared__ float wsum[NT / 32];

    const int tid = threadIdx.x;
    const int gx0 = blockIdx.x * TW - HALO;
    const int gy0 = blockIdx.y * TH - HALO;
    const size_t pbase = (size_t)blockIdx.z * (IMG * IMG);
    const float* p1 = img1 + pbase;
    const float* p2 = img2 + pbase;

    // ---- Phase 1: global -> smem. s=(i1+i2)*0.5+1, d=(i1-i2)*0.5.
    //      Coalesced: 32 contiguous cols per warp-row, 8 rows/pass. ----
    {
        const int c  = tid & 31;
        const int r8 = tid >> 5;
        #pragma unroll
        for (int rr = r8; rr < INH; rr += 8) {
            const int gy = gy0 + rr;
            const bool rowok = (gy >= 0) && (gy < IMG);
            const float* q1 = p1 + (size_t)gy * IMG;
            const float* q2 = p2 + (size_t)gy * IMG;
            #pragma unroll
            for (int cb = 0; cb < 3; cb++) {
                int cc = c + 32 * cb;
                if (cb < 2 || cc < INWP) {
                    int gx = gx0 + cc;
                    float vs = 0.f, vd = 0.f;
                    if (rowok && cc < INW && gx >= 0 && gx < IMG) {
                        float a = q1[gx], b = q2[gx];
                        vs = fmaf(a + b, 0.5f, 1.0f);
                        vd = (a - b) * 0.5f;
                    }
                    ss[rr * INWP + cc] = vs;
                    sd[rr * INWP + cc] = vd;
                }
            }
        }
    }
    __syncthreads();

    // ---- Phase 2: horizontal blur, 8 output cols/thread, 256 tasks ----
    {
        const int row = tid >> 3;           // 0..31
        const int c8  = (tid & 7) << 3;     // 0,8,...,56
        hblur8(ss, sh + 0 * HPLANE, sh + 2 * HPLANE, row, c8);  // s half
        hblur8(sd, sh + 1 * HPLANE, sh + 3 * HPLANE, row, c8);  // d half
    }
    __syncthreads();

    // ---- Phase 3: vertical blur + ssim. 64 cols x 4 groups (6,6,5,5 rows) ----
    const int col = tid & 63;
    const int g   = tid >> 6;               // 0..3
    const int r_start = (g < 3) ? 6 * g : 17;    // 0,6,12,17
    const int nrows   = (g < 2) ? 6 : 5;

    float acc0[6], acc1[6], acc2[6], acc3[6];
    #pragma unroll
    for (int j = 0; j < 6; j++) {
        acc0[j] = 0.f; acc1[j] = 0.f; acc2[j] = 0.f; acc3[j] = 0.f;
    }

    #pragma unroll
    for (int i = 0; i < 16; i++) {
        if (i < nrows + 10) {
            int ri = r_start + i;
            if (ri > INH - 1) ri = INH - 1;   // safety clamp (never hit when guarded)
            const float* hp = sh + ri * TW + col;
            float h0 = hp[0 * HPLANE];
            float h1 = hp[1 * HPLANE];
            float h2 = hp[2 * HPLANE];
            float h3 = hp[3 * HPLANE];
            #pragma unroll
            for (int j = 0; j < 6; j++) {
                int k = i - j;
                if (k >= 0 && k < 11) {
                    float w = gw(k);
                    acc0[j] = fmaf(h0, w, acc0[j]);
                    acc1[j] = fmaf(h1, w, acc1[j]);
                    acc2[j] = fmaf(h2, w, acc2[j]);
                    acc3[j] = fmaf(h3, w, acc3[j]);
                }
            }
        }
    }

    const float C1 = 0.0001f;   // 0.01^2
    const float C2 = 0.0009f;   // 0.03^2
    const int   gyb = blockIdx.y * TH + r_start;
    float tsum = 0.f;
    #pragma unroll
    for (int j = 0; j < 6; j++) {
        bool valid = (j < nrows) && (gyb + j < IMG);
        if (valid) {
            float Bs  = acc0[j], Bd  = acc1[j];
            float Bs2 = acc2[j], Bd2 = acc3[j];
            float bss = Bs * Bs, bdd = Bd * Bd;
            float mu12   = 0.25f * (bss - bdd);        // mu1*mu2
            float musq   = 0.50f * (bss + bdd);        // mu1^2 + mu2^2
            float sig12  = 0.25f * (Bs2 - Bd2) - mu12; // sigma12
            float sigsum = 0.50f * (Bs2 + Bd2) - musq; // sigma1^2+sigma2^2
            float num = fmaf(2.f, mu12,  C1) * fmaf(2.f, sig12, C2);
            float den = (musq + C1) * (sigsum + C2);
            tsum += __fdividef(num, den);
        }
    }

    // ---- Reduction: warp shuffle -> static wsum (1 barrier) -> STG ----
    #pragma unroll
    for (int off = 16; off; off >>= 1)
        tsum += __shfl_xor_sync(0xffffffffu, tsum, off);

    if ((tid & 31) == 0) wsum[tid >> 5] = tsum;
    __syncthreads();
    if (tid == 0) {
        float bs = 0.f;
        #pragma unroll
        for (int i = 0; i < NT / 32; i++) bs += wsum[i];
        int slot = (blockIdx.z * GY + blockIdx.y) * GX + blockIdx.x;
        g_part[slot] = bs;
    }
}

__global__ __launch_bounds__(1024)
void ssim_reduce1() {
    __shared__ float ws[32];
    const int tid = threadIdx.x;
    float s = g_part[blockIdx.x * 1024 + tid];

    #pragma unroll
    for (int off = 16; off; off >>= 1)
        s += __shfl_xor_sync(0xffffffffu, s, off);
    if ((tid & 31) == 0) ws[tid >> 5] = s;
    __syncthreads();
    if (tid < 32) {
        float t = ws[tid];
        #pragma unroll
        for (int off = 16; off; off >>= 1)
            t += __shfl_xor_sync(0xffffffffu, t, off);
        if (tid == 0) g_part2[blockIdx.x] = t;
    }
}

__global__ void ssim_fin(float* out, double inv_n) {
    const int tid = threadIdx.x;   // 32 threads
    double s = (tid < 18) ? (double)g_part2[tid] : 0.0;
    #pragma unroll
    for (int off = 16; off; off >>= 1)
        s += __shfl_xor_sync(0xffffffffu, s, off);
    if (tid == 0) out[0] = 1.0f - (float)(s * inv_n);
}

extern "C" void kernel_launch(void* const* d_in, const int* in_sizes, int n_in,
                              void* d_out, int out_size) {
    const float* img1 = (const float*)d_in[0];
    const float* img2 = (const float*)d_in[1];
    (void)n_in; (void)out_size; (void)in_sizes;

    cudaFuncSetAttribute(ssim_main, cudaFuncAttributeMaxDynamicSharedMemorySize,
                         SMEM_BYTES);

    dim3 grid(GX, GY, PL);
    ssim_main<<<grid, NT, SMEM_BYTES>>>(img1, img2);

    ssim_reduce1<<<18, 1024>>>();
    double inv_n = 1.0 / ((double)PL * IMG * IMG);
    ssim_fin<<<1, 32>>>((float*)d_out, inv_n);
}